// round 15
// baseline (speedup 1.0000x reference)
#include <cuda_runtime.h>
#include <cuda_bf16.h>
#include <cstdint>

// Problem constants
#define BATCH 32
#define DIM   256
#define HW    1024
#define NPTS  32768
#define KCODE 1024
#define ZQ_ELEMS 8388608
#define IDX_OFF  ZQ_ELEMS
#define LOSS_OFF (ZQ_ELEMS + NPTS)

#define NSLOT 3           // top-3 per (thread,row) slot
#define NCROW 24          // 8 slots * 3 candidates per row
#define MARGIN 7e-4f

// Scratch (device globals)
__device__ float          g_zt [NPTS * DIM];     // z^T fp32 [N,D]
__device__ __nv_bfloat16  g_zth[NPTS * DIM];     // z^T bf16
__device__ __nv_bfloat16  g_cbh[KCODE * DIM];    // codebook bf16
__device__ int            g_idx[NPTS];
__device__ float          g_normE[KCODE];        // t2
__device__ float          g_t1[NPTS];            // t1 (sequential emulation)
__device__ double         g_loss;

// ================= generic PTX helpers =================
__device__ __forceinline__ uint32_t smem_u32(const void* p) {
    uint32_t a;
    asm("{ .reg .u64 t; cvta.to.shared.u64 t, %1; cvt.u32.u64 %0, t; }" : "=r"(a) : "l"(p));
    return a;
}
#define CP_ASYNC16(dst, src) \
    asm volatile("cp.async.cg.shared.global [%0], [%1], 16;" :: "r"(dst), "l"(src) : "memory")
#define CP_COMMIT() asm volatile("cp.async.commit_group;" ::: "memory")
#define CP_WAIT0()  asm volatile("cp.async.wait_group 0;" ::: "memory")
#define CP_WAIT1()  asm volatile("cp.async.wait_group 1;" ::: "memory")

#define LDSM4(r0, r1, r2, r3, addr) \
    asm volatile("ldmatrix.sync.aligned.m8n8.x4.shared.b16 {%0,%1,%2,%3}, [%4];" \
        : "=r"(r0), "=r"(r1), "=r"(r2), "=r"(r3) : "r"(addr))

#define MMA16816(C, A, b0, b1) \
    asm volatile("mma.sync.aligned.m16n8k16.row.col.f32.bf16.bf16.f32 " \
        "{%0,%1,%2,%3},{%4,%5,%6,%7},{%8,%9},{%0,%1,%2,%3};" \
        : "+f"((C)[0]), "+f"((C)[1]), "+f"((C)[2]), "+f"((C)[3]) \
        : "r"((A)[0]), "r"((A)[1]), "r"((A)[2]), "r"((A)[3]), "r"(b0), "r"(b1))

// swizzled smem offset for bf16 tile rows of 512B, 16B chunks
__device__ __forceinline__ uint32_t sw_off(int row, int c16) {
    return (uint32_t)(row * 512 + ((c16 ^ (row & 7)) << 4));
}

// ================= Kernel 1: FUSED prep (transpose+t1) + codebook norms =========
__global__ __launch_bounds__(256) void prep_k(const float* __restrict__ z,
                                              const float* __restrict__ cb) {
    const int bid = blockIdx.x;
    const int tid = threadIdx.x;
    if (bid < 1024) {
        __shared__ float sbuf[32][257];       // [p][d], 257 kills bank conflicts
        const int b  = bid >> 5;
        const int p0 = (bid & 31) << 5;
        const int tx = tid & 31, ty = tid >> 5;
        const float* src = z + (size_t)b * DIM * HW + p0;
        for (int d = ty; d < DIM; d += 8)
            sbuf[tx][d] = src[(size_t)d * HW + tx];
        __syncthreads();
        const int n0 = (b << 10) + p0;
        #pragma unroll 4
        for (int p = 0; p < 32; p++) {
            float v = sbuf[p][tid];
            size_t o = (size_t)(n0 + p) * DIM + tid;
            g_zt[o]  = v;
            g_zth[o] = __float2bfloat16(v);
        }
        if (tid < 32) {
            const float* row = &sbuf[tid][0];
            float acc = 0.0f;
            #pragma unroll 8
            for (int d = 0; d < DIM; d++)
                acc = __fadd_rn(acc, __fmul_rn(row[d], row[d]));   // strict seq chain
            g_t1[n0 + tid] = acc;
        }
    } else {
        const int k    = ((bid - 1024) << 3) + (tid >> 5);
        const int lane = tid & 31;
        const float4* cp = (const float4*)&cb[(size_t)k * DIM + lane * 8];
        float4 a = cp[0], b4 = cp[1];
        __nv_bfloat162 h0 = __floats2bfloat162_rn(a.x, a.y);
        __nv_bfloat162 h1 = __floats2bfloat162_rn(a.z, a.w);
        __nv_bfloat162 h2 = __floats2bfloat162_rn(b4.x, b4.y);
        __nv_bfloat162 h3 = __floats2bfloat162_rn(b4.z, b4.w);
        uint4 u;
        u.x = *(uint32_t*)&h0; u.y = *(uint32_t*)&h1;
        u.z = *(uint32_t*)&h2; u.w = *(uint32_t*)&h3;
        ((uint4*)g_cbh)[(size_t)k * 32 + lane] = u;
        float s = 0.0f;
        s = __fmaf_rn(a.x, a.x, s);  s = __fmaf_rn(a.y, a.y, s);
        s = __fmaf_rn(a.z, a.z, s);  s = __fmaf_rn(a.w, a.w, s);
        s = __fmaf_rn(b4.x, b4.x, s); s = __fmaf_rn(b4.y, b4.y, s);
        s = __fmaf_rn(b4.z, b4.z, s); s = __fmaf_rn(b4.w, b4.w, s);
        #pragma unroll
        for (int o = 16; o; o >>= 1) s += __shfl_xor_sync(0xffffffffu, s, o);
        if (lane == 0) g_normE[k] = s;
        if (bid == 1024 && tid == 0) g_loss = 0.0;
    }
}

// ================= Kernel 2: HMMA bf16 GEMM + full in-CTA resolve & rescore =====
// smem: A 32KB | B0 32KB | B1 32KB | NE 4KB = 100KB -> 2 CTAs/SM
#define AS_OFF 0
#define BS_OFF 32768
#define NE_OFF 98304
#define HM_SMEM 102400

__global__ __launch_bounds__(128, 2) void gemm_hmma_k(float* __restrict__ out, int write_idx) {
    extern __shared__ char smem[];
    const uint32_t sb = smem_u32(smem);
    const int tid  = threadIdx.x;
    const int lane = tid & 31;
    const int wid  = tid >> 5;
    const int wm   = wid & 1;
    const int wn   = wid >> 1;
    const int m0   = blockIdx.x * 64;

    #pragma unroll 4
    for (int i = tid; i < 2048; i += 128) {
        int row = i >> 5, c16 = i & 31;
        const __nv_bfloat16* src = &g_zth[(size_t)(m0 + row) * DIM + c16 * 8];
        CP_ASYNC16(sb + AS_OFF + sw_off(row, c16), (const void*)src);
    }
    #pragma unroll 4
    for (int i = tid; i < 2048; i += 128) {
        int row = i >> 5, c16 = i & 31;
        const __nv_bfloat16* src = &g_cbh[(size_t)row * DIM + c16 * 8];
        CP_ASYNC16(sb + BS_OFF + sw_off(row, c16), (const void*)src);
    }
    #pragma unroll
    for (int i = tid; i < 256; i += 128)
        CP_ASYNC16(sb + NE_OFF + i * 16, (const void*)&g_normE[i * 4]);
    CP_COMMIT();
    #pragma unroll 4
    for (int i = tid; i < 2048; i += 128) {
        int row = i >> 5, c16 = i & 31;
        const __nv_bfloat16* src = &g_cbh[(size_t)(64 + row) * DIM + c16 * 8];
        CP_ASYNC16(sb + BS_OFF + 32768 + sw_off(row, c16), (const void*)src);
    }
    CP_COMMIT();

    float tv[4][NSLOT];
    int   ts[4][NSLOT];
    #pragma unroll
    for (int s = 0; s < 4; s++)
        #pragma unroll
        for (int j = 0; j < NSLOT; j++) { tv[s][j] = 3.4e38f; ts[s][j] = 0; }

    const float2* nep = (const float2*)(smem + NE_OFF);
    const float*  nef = (const float*)(smem + NE_OFF);

    const int arow = wm * 32 + (lane & 15);
    const int acol_sel = (lane >> 4);
    const int brow0 = wn * 32 + ((lane >> 4) & 1) * 8 + (lane & 7);
    const int bcol_sel = ((lane >> 3) & 1);

    for (int c = 0; c < 16; ++c) {
        if (c < 15) CP_WAIT1(); else CP_WAIT0();
        __syncthreads();

        const uint32_t Bbase = sb + BS_OFF + ((c & 1) << 15);
        float C[2][4][4];
        #pragma unroll
        for (int mt = 0; mt < 2; mt++)
            #pragma unroll
            for (int nt = 0; nt < 4; nt++)
                #pragma unroll
                for (int q = 0; q < 4; q++) C[mt][nt][q] = 0.0f;

        uint32_t a[2][2][4], b[2][2][4];
        {
            int c16 = acol_sel;
            LDSM4(a[0][0][0], a[0][0][1], a[0][0][2], a[0][0][3], sb + AS_OFF + sw_off(arow,      c16));
            LDSM4(a[0][1][0], a[0][1][1], a[0][1][2], a[0][1][3], sb + AS_OFF + sw_off(arow + 16, c16));
            int bc = bcol_sel;
            LDSM4(b[0][0][0], b[0][0][1], b[0][0][2], b[0][0][3], Bbase + sw_off(brow0,      bc));
            LDSM4(b[0][1][0], b[0][1][1], b[0][1][2], b[0][1][3], Bbase + sw_off(brow0 + 16, bc));
        }

        #pragma unroll
        for (int st = 0; st < 16; ++st) {
            const int cur = st & 1, nxt = cur ^ 1;
            if (st < 15) {
                int c16 = (st + 1) * 2 + acol_sel;
                LDSM4(a[nxt][0][0], a[nxt][0][1], a[nxt][0][2], a[nxt][0][3], sb + AS_OFF + sw_off(arow,      c16));
                LDSM4(a[nxt][1][0], a[nxt][1][1], a[nxt][1][2], a[nxt][1][3], sb + AS_OFF + sw_off(arow + 16, c16));
                int bc = (st + 1) * 2 + bcol_sel;
                LDSM4(b[nxt][0][0], b[nxt][0][1], b[nxt][0][2], b[nxt][0][3], Bbase + sw_off(brow0,      bc));
                LDSM4(b[nxt][1][0], b[nxt][1][1], b[nxt][1][2], b[nxt][1][3], Bbase + sw_off(brow0 + 16, bc));
            }
            #pragma unroll
            for (int mt = 0; mt < 2; mt++)
                #pragma unroll
                for (int nt = 0; nt < 4; nt++)
                    MMA16816(C[mt][nt], a[cur][mt], b[cur][nt >> 1][(nt & 1) * 2], b[cur][nt >> 1][(nt & 1) * 2 + 1]);
        }
        __syncthreads();

        if (c + 2 < 16) {
            #pragma unroll 4
            for (int i = tid; i < 2048; i += 128) {
                int row = i >> 5, c16 = i & 31;
                const __nv_bfloat16* src = &g_cbh[(size_t)((c + 2) * 64 + row) * DIM + c16 * 8];
                CP_ASYNC16(Bbase + sw_off(row, c16), (const void*)src);
            }
            CP_COMMIT();
        }

        #pragma unroll
        for (int mt = 0; mt < 2; mt++) {
            #pragma unroll
            for (int nt = 0; nt < 4; nt++) {
                int col = c * 64 + wn * 32 + nt * 8 + ((lane & 3) << 1);
                float2 ne = nep[col >> 1];
                float dv[4];
                dv[0] = __fmaf_rn(-2.0f, C[mt][nt][0], ne.x);
                dv[1] = __fmaf_rn(-2.0f, C[mt][nt][1], ne.y);
                dv[2] = __fmaf_rn(-2.0f, C[mt][nt][2], ne.x);
                dv[3] = __fmaf_rn(-2.0f, C[mt][nt][3], ne.y);
                #pragma unroll
                for (int q = 0; q < 4; q++) {
                    const int s = mt * 2 + (q >> 1);
                    const int idx = col + (q & 1);
                    const float v = dv[q];
                    if (v < tv[s][2]) {
                        if (v < tv[s][1]) {
                            tv[s][2] = tv[s][1]; ts[s][2] = ts[s][1];
                            if (v < tv[s][0]) {
                                tv[s][1] = tv[s][0]; ts[s][1] = ts[s][0];
                                tv[s][0] = v;        ts[s][0] = idx;
                            } else { tv[s][1] = v; ts[s][1] = idx; }
                        } else { tv[s][2] = v; ts[s][2] = idx; }
                    }
                }
            }
        }
    }

    // ---- fused resolve + in-CTA exact rescore (B smem reused as scratch) ----
    float*  sV    = (float*)(smem + BS_OFF);               // 64*24 f32
    int*    sI    = (int*)  (smem + BS_OFF + 8192);
    float*  st1   = (float*)(smem + BS_OFF + 16384);       // 64 f32
    double* swl   = (double*)(smem + BS_OFF + 16896);      // 4 doubles
    int*    slist = (int*)  (smem + BS_OFF + 16960);       // ambiguous local rows
    int*    scnt  = (int*)  (smem + BS_OFF + 17224);

    if (tid == 0) *scnt = 0;
    if (tid < 64) st1[tid] = g_t1[m0 + tid];
    #pragma unroll
    for (int mt = 0; mt < 2; mt++) {
        #pragma unroll
        for (int h = 0; h < 2; h++) {
            int r    = wm * 32 + mt * 16 + h * 8 + (lane >> 2);
            int slot = wn * 4 + (lane & 3);
            int s = mt * 2 + h;
            #pragma unroll
            for (int j = 0; j < NSLOT; j++) {
                sV[r * 24 + slot * 3 + j] = tv[s][j];
                sI[r * 24 + slot * 3 + j] = ts[s][j];
            }
        }
    }
    __syncthreads();

    double lossAcc = 0.0;
    for (int rr = 0; rr < 16; rr++) {
        const int r = wid * 16 + rr;
        float v = (lane < NCROW) ? sV[r * 24 + lane] : 3.4e38f;
        int  ix = (lane < NCROW) ? sI[r * 24 + lane] : 0;
        float vmin = v;
        #pragma unroll
        for (int o = 16; o; o >>= 1) vmin = fminf(vmin, __shfl_xor_sync(0xffffffffu, vmin, o));
        unsigned m = __ballot_sync(0xffffffffu, v <= vmin + MARGIN);
        if (__popc(m) == 1) {
            int wl = __ffs(m) - 1;
            int bi   = __shfl_sync(0xffffffffu, ix, wl);
            float vw = __shfl_sync(0xffffffffu, v, wl);
            if (lane == 0) {
                g_idx[m0 + r] = bi;
                if (write_idx) out[IDX_OFF + m0 + r] = (float)bi;
                lossAcc += (double)(st1[r] + vw);      // approx dist; err ~3e-5 abs
            }
        } else {
            if (lane == 0) slist[atomicAdd(scnt, 1)] = r;
        }
    }
    __syncthreads();

    // in-CTA exact fp32 rescore of ambiguous rows (same semantics as rescore_k)
    const int cnt = *scnt;
    for (int j = wid; j < cnt; j += 4) {
        const int r   = slist[j];
        const int row = m0 + r;
        float v = (lane < NCROW) ? sV[r * 24 + lane] : 3.4e38f;
        int  i1 = (lane < NCROW) ? sI[r * 24 + lane] : 0;
        float vmin = v;
        #pragma unroll
        for (int o = 16; o; o >>= 1) vmin = fminf(vmin, __shfl_xor_sync(0xffffffffu, vmin, o));
        unsigned m1 = __ballot_sync(0xffffffffu, v <= vmin + MARGIN);

        const float4* zp = (const float4*)&g_zt[(size_t)row * DIM + lane * 8];
        const float4 za = zp[0], zb = zp[1];
        const float t1 = st1[r];
        float bestD = 3.4e38f;
        int bestI = 0x7fffffff;
        while (m1) {
            int l = __ffs(m1) - 1; m1 &= m1 - 1;
            int idx = __shfl_sync(0xffffffffu, i1, l);
            const float4* cp = (const float4*)&g_zt[0];   // placeholder (unused)
            (void)cp;
            const float4* cbp = (const float4*)((const char*)nullptr);
            (void)cbp;
            // codebook fp32 rows live in global cb — passed via g_cb pointer below
            extern __device__ const float* g_cbPtr;
            const float4* c4 = (const float4*)&g_cbPtr[(size_t)idx * DIM + lane * 8];
            float4 ca = c4[0], cb4 = c4[1];
            float p = 0.0f;
            p = __fmaf_rn(za.x, ca.x, p);  p = __fmaf_rn(za.y, ca.y, p);
            p = __fmaf_rn(za.z, ca.z, p);  p = __fmaf_rn(za.w, ca.w, p);
            p = __fmaf_rn(zb.x, cb4.x, p); p = __fmaf_rn(zb.y, cb4.y, p);
            p = __fmaf_rn(zb.z, cb4.z, p); p = __fmaf_rn(zb.w, cb4.w, p);
            #pragma unroll
            for (int o = 16; o; o >>= 1) p += __shfl_xor_sync(0xffffffffu, p, o);
            float dd = __fsub_rn(__fadd_rn(t1, nef[idx]), __fmul_rn(2.0f, p));
            if (dd < bestD || (dd == bestD && idx < bestI)) { bestD = dd; bestI = idx; }
        }
        if (lane == 0) {
            g_idx[row] = bestI;
            if (write_idx) out[IDX_OFF + row] = (float)bestI;
            lossAcc += (double)bestD;                  // exact dist
        }
    }
    if (lane == 0) swl[wid] = lossAcc;
    __syncthreads();
    if (tid == 0) atomicAdd(&g_loss, swl[0] + swl[1] + swl[2] + swl[3]);
}

// fp32 codebook pointer for the in-gemm rescore (set per launch; constant value)
__device__ const float* g_cbPtr;
__global__ void set_cbptr_k(const float* cb) { g_cbPtr = cb; }

// ================= Kernel 3: gather z_q, d-split x8 blocks, float4 writes =======
__global__ __launch_bounds__(256) void gather_k(const float* __restrict__ z,
                                                const float* __restrict__ cb,
                                                float* __restrict__ out,
                                                int write_loss) {
    __shared__ float sq[64 * 33];      // [p][d_local], pad 33
    __shared__ int   sidx[64];
    const int n0 = blockIdx.x * 64;
    const int d0 = blockIdx.y * 32;
    const int b  = n0 >> 10, p0 = n0 & (HW - 1);
    const int tid = threadIdx.x;

    if (tid < 64) sidx[tid] = g_idx[n0 + tid];
    __syncthreads();
    #pragma unroll
    for (int i = tid; i < 512; i += 256) {
        int r = i >> 3, c4 = i & 7;
        float4 v = ((const float4*)cb)[(size_t)sidx[r] * 64 + (d0 >> 2) + c4];
        float* dst = &sq[r * 33 + c4 * 4];
        dst[0] = v.x; dst[1] = v.y; dst[2] = v.z; dst[3] = v.w;
    }
    __syncthreads();

    const int pq = tid & 15;
    const int dd = tid >> 4;
    const size_t base = (size_t)b * DIM * HW + p0 + pq * 4;
    #pragma unroll
    for (int ii = 0; ii < 2; ii++) {
        const int dl = ii * 16 + dd;
        const size_t off = base + (size_t)(d0 + dl) * HW;
        float4 zv = *(const float4*)&z[off];
        float q0 = sq[(pq * 4 + 0) * 33 + dl];
        float q1 = sq[(pq * 4 + 1) * 33 + dl];
        float q2 = sq[(pq * 4 + 2) * 33 + dl];
        float q3 = sq[(pq * 4 + 3) * 33 + dl];
        float4 o;
        float dx = __fsub_rn(q0, zv.x); o.x = __fadd_rn(zv.x, dx);
        float dy = __fsub_rn(q1, zv.y); o.y = __fadd_rn(zv.y, dy);
        float dz = __fsub_rn(q2, zv.z); o.z = __fadd_rn(zv.z, dz);
        float dw = __fsub_rn(q3, zv.w); o.w = __fadd_rn(zv.w, dw);
        *(float4*)&out[off] = o;                      // == reference STE per element
    }
    if (blockIdx.x == 0 && blockIdx.y == 0 && tid == 0 && write_loss)
        out[LOSS_OFF] = (float)(1.25 * g_loss / (double)ZQ_ELEMS);
}

extern "C" void kernel_launch(void* const* d_in, const int* in_sizes, int n_in,
                              void* d_out, int out_size) {
    const float* z  = (const float*)d_in[0];
    const float* cb = (const float*)d_in[1];
    float* out = (float*)d_out;

    cudaFuncSetAttribute(gemm_hmma_k, cudaFuncAttributeMaxDynamicSharedMemorySize, HM_SMEM);

    int write_idx  = (out_size >= IDX_OFF + NPTS);
    int write_loss = (out_size >= LOSS_OFF + 1);

    set_cbptr_k<<<1, 1>>>(cb);
    prep_k<<<1152, 256>>>(z, cb);
    gemm_hmma_k<<<NPTS / 64, 128, HM_SMEM>>>(out, write_idx);
    gather_k<<<dim3(NPTS / 64, 8), 256>>>(z, cb, out, write_loss);
}

// round 16
// speedup vs baseline: 1.0155x; 1.0155x over previous
#include <cuda_runtime.h>
#include <cuda_bf16.h>
#include <cstdint>

// Problem constants
#define BATCH 32
#define DIM   256
#define HW    1024
#define NPTS  32768
#define KCODE 1024
#define ZQ_ELEMS 8388608
#define IDX_OFF  ZQ_ELEMS
#define LOSS_OFF (ZQ_ELEMS + NPTS)

#define NSLOT 3           // top-3 per (thread,row) slot
#define NCROW 24          // 8 slots * 3 candidates per row
#define MARGIN 7e-4f

// Scratch (device globals)
__device__ __nv_bfloat16  g_zth[NPTS * DIM];     // z^T bf16
__device__ __nv_bfloat16  g_cbh[KCODE * DIM];    // codebook bf16
__device__ int            g_idx[NPTS];
__device__ float          g_normE[KCODE];        // t2
__device__ float          g_t1[NPTS];            // t1 (sequential emulation)
__device__ double         g_loss;

// ================= generic PTX helpers =================
__device__ __forceinline__ uint32_t smem_u32(const void* p) {
    uint32_t a;
    asm("{ .reg .u64 t; cvta.to.shared.u64 t, %1; cvt.u32.u64 %0, t; }" : "=r"(a) : "l"(p));
    return a;
}
#define CP_ASYNC16(dst, src) \
    asm volatile("cp.async.cg.shared.global [%0], [%1], 16;" :: "r"(dst), "l"(src) : "memory")
#define CP_COMMIT() asm volatile("cp.async.commit_group;" ::: "memory")
#define CP_WAIT0()  asm volatile("cp.async.wait_group 0;" ::: "memory")
#define CP_WAIT1()  asm volatile("cp.async.wait_group 1;" ::: "memory")

#define LDSM4(r0, r1, r2, r3, addr) \
    asm volatile("ldmatrix.sync.aligned.m8n8.x4.shared.b16 {%0,%1,%2,%3}, [%4];" \
        : "=r"(r0), "=r"(r1), "=r"(r2), "=r"(r3) : "r"(addr))

#define MMA16816(C, A, b0, b1) \
    asm volatile("mma.sync.aligned.m16n8k16.row.col.f32.bf16.bf16.f32 " \
        "{%0,%1,%2,%3},{%4,%5,%6,%7},{%8,%9},{%0,%1,%2,%3};" \
        : "+f"((C)[0]), "+f"((C)[1]), "+f"((C)[2]), "+f"((C)[3]) \
        : "r"((A)[0]), "r"((A)[1]), "r"((A)[2]), "r"((A)[3]), "r"(b0), "r"(b1))

// swizzled smem offset for bf16 tile rows of 512B, 16B chunks
__device__ __forceinline__ uint32_t sw_off(int row, int c16) {
    return (uint32_t)(row * 512 + ((c16 ^ (row & 7)) << 4));
}

// ================= Kernel 1: FUSED prep (transpose+t1) + codebook norms =========
// z -> zth (bf16) + t1 only (no fp32 transpose copy anymore).
__global__ __launch_bounds__(256) void prep_k(const float* __restrict__ z,
                                              const float* __restrict__ cb) {
    const int bid = blockIdx.x;
    const int tid = threadIdx.x;
    if (bid < 1024) {
        __shared__ float sbuf[32][257];       // [p][d], 257 kills bank conflicts
        const int b  = bid >> 5;
        const int p0 = (bid & 31) << 5;
        const int tx = tid & 31, ty = tid >> 5;
        const float* src = z + (size_t)b * DIM * HW + p0;
        for (int d = ty; d < DIM; d += 8)
            sbuf[tx][d] = src[(size_t)d * HW + tx];
        __syncthreads();
        const int n0 = (b << 10) + p0;
        #pragma unroll 4
        for (int p = 0; p < 32; p++) {
            g_zth[(size_t)(n0 + p) * DIM + tid] = __float2bfloat16(sbuf[p][tid]);
        }
        if (tid < 32) {
            const float* row = &sbuf[tid][0];
            float acc = 0.0f;
            #pragma unroll 8
            for (int d = 0; d < DIM; d++)
                acc = __fadd_rn(acc, __fmul_rn(row[d], row[d]));   // strict seq chain
            g_t1[n0 + tid] = acc;
        }
    } else {
        const int k    = ((bid - 1024) << 3) + (tid >> 5);
        const int lane = tid & 31;
        const float4* cp = (const float4*)&cb[(size_t)k * DIM + lane * 8];
        float4 a = cp[0], b4 = cp[1];
        __nv_bfloat162 h0 = __floats2bfloat162_rn(a.x, a.y);
        __nv_bfloat162 h1 = __floats2bfloat162_rn(a.z, a.w);
        __nv_bfloat162 h2 = __floats2bfloat162_rn(b4.x, b4.y);
        __nv_bfloat162 h3 = __floats2bfloat162_rn(b4.z, b4.w);
        uint4 u;
        u.x = *(uint32_t*)&h0; u.y = *(uint32_t*)&h1;
        u.z = *(uint32_t*)&h2; u.w = *(uint32_t*)&h3;
        ((uint4*)g_cbh)[(size_t)k * 32 + lane] = u;
        float s = 0.0f;
        s = __fmaf_rn(a.x, a.x, s);  s = __fmaf_rn(a.y, a.y, s);
        s = __fmaf_rn(a.z, a.z, s);  s = __fmaf_rn(a.w, a.w, s);
        s = __fmaf_rn(b4.x, b4.x, s); s = __fmaf_rn(b4.y, b4.y, s);
        s = __fmaf_rn(b4.z, b4.z, s); s = __fmaf_rn(b4.w, b4.w, s);
        #pragma unroll
        for (int o = 16; o; o >>= 1) s += __shfl_xor_sync(0xffffffffu, s, o);
        if (lane == 0) g_normE[k] = s;
        if (bid == 1024 && tid == 0) g_loss = 0.0;
    }
}

// ================= Kernel 2: HMMA bf16 GEMM + full in-CTA resolve & rescore =====
// smem: A 32KB | B0 32KB | B1 32KB | NE 4KB = 100KB -> 2 CTAs/SM
#define AS_OFF 0
#define BS_OFF 32768
#define NE_OFF 98304
#define HM_SMEM 102400

__global__ __launch_bounds__(128, 2) void gemm_hmma_k(const float* __restrict__ z,
                                                      const float* __restrict__ cb,
                                                      float* __restrict__ out, int write_idx) {
    extern __shared__ char smem[];
    const uint32_t sb = smem_u32(smem);
    const int tid  = threadIdx.x;
    const int lane = tid & 31;
    const int wid  = tid >> 5;
    const int wm   = wid & 1;
    const int wn   = wid >> 1;
    const int m0   = blockIdx.x * 64;

    #pragma unroll 4
    for (int i = tid; i < 2048; i += 128) {
        int row = i >> 5, c16 = i & 31;
        const __nv_bfloat16* src = &g_zth[(size_t)(m0 + row) * DIM + c16 * 8];
        CP_ASYNC16(sb + AS_OFF + sw_off(row, c16), (const void*)src);
    }
    #pragma unroll 4
    for (int i = tid; i < 2048; i += 128) {
        int row = i >> 5, c16 = i & 31;
        const __nv_bfloat16* src = &g_cbh[(size_t)row * DIM + c16 * 8];
        CP_ASYNC16(sb + BS_OFF + sw_off(row, c16), (const void*)src);
    }
    #pragma unroll
    for (int i = tid; i < 256; i += 128)
        CP_ASYNC16(sb + NE_OFF + i * 16, (const void*)&g_normE[i * 4]);
    CP_COMMIT();
    #pragma unroll 4
    for (int i = tid; i < 2048; i += 128) {
        int row = i >> 5, c16 = i & 31;
        const __nv_bfloat16* src = &g_cbh[(size_t)(64 + row) * DIM + c16 * 8];
        CP_ASYNC16(sb + BS_OFF + 32768 + sw_off(row, c16), (const void*)src);
    }
    CP_COMMIT();

    float tv[4][NSLOT];
    int   ts[4][NSLOT];
    #pragma unroll
    for (int s = 0; s < 4; s++)
        #pragma unroll
        for (int j = 0; j < NSLOT; j++) { tv[s][j] = 3.4e38f; ts[s][j] = 0; }

    const float2* nep = (const float2*)(smem + NE_OFF);
    const float*  nef = (const float*)(smem + NE_OFF);

    const int arow = wm * 32 + (lane & 15);
    const int acol_sel = (lane >> 4);
    const int brow0 = wn * 32 + ((lane >> 4) & 1) * 8 + (lane & 7);
    const int bcol_sel = ((lane >> 3) & 1);

    for (int c = 0; c < 16; ++c) {
        if (c < 15) CP_WAIT1(); else CP_WAIT0();
        __syncthreads();

        const uint32_t Bbase = sb + BS_OFF + ((c & 1) << 15);
        float C[2][4][4];
        #pragma unroll
        for (int mt = 0; mt < 2; mt++)
            #pragma unroll
            for (int nt = 0; nt < 4; nt++)
                #pragma unroll
                for (int q = 0; q < 4; q++) C[mt][nt][q] = 0.0f;

        uint32_t a[2][2][4], b[2][2][4];
        {
            int c16 = acol_sel;
            LDSM4(a[0][0][0], a[0][0][1], a[0][0][2], a[0][0][3], sb + AS_OFF + sw_off(arow,      c16));
            LDSM4(a[0][1][0], a[0][1][1], a[0][1][2], a[0][1][3], sb + AS_OFF + sw_off(arow + 16, c16));
            int bc = bcol_sel;
            LDSM4(b[0][0][0], b[0][0][1], b[0][0][2], b[0][0][3], Bbase + sw_off(brow0,      bc));
            LDSM4(b[0][1][0], b[0][1][1], b[0][1][2], b[0][1][3], Bbase + sw_off(brow0 + 16, bc));
        }

        #pragma unroll
        for (int st = 0; st < 16; ++st) {
            const int cur = st & 1, nxt = cur ^ 1;
            if (st < 15) {
                int c16 = (st + 1) * 2 + acol_sel;
                LDSM4(a[nxt][0][0], a[nxt][0][1], a[nxt][0][2], a[nxt][0][3], sb + AS_OFF + sw_off(arow,      c16));
                LDSM4(a[nxt][1][0], a[nxt][1][1], a[nxt][1][2], a[nxt][1][3], sb + AS_OFF + sw_off(arow + 16, c16));
                int bc = (st + 1) * 2 + bcol_sel;
                LDSM4(b[nxt][0][0], b[nxt][0][1], b[nxt][0][2], b[nxt][0][3], Bbase + sw_off(brow0,      bc));
                LDSM4(b[nxt][1][0], b[nxt][1][1], b[nxt][1][2], b[nxt][1][3], Bbase + sw_off(brow0 + 16, bc));
            }
            #pragma unroll
            for (int mt = 0; mt < 2; mt++)
                #pragma unroll
                for (int nt = 0; nt < 4; nt++)
                    MMA16816(C[mt][nt], a[cur][mt], b[cur][nt >> 1][(nt & 1) * 2], b[cur][nt >> 1][(nt & 1) * 2 + 1]);
        }
        __syncthreads();

        if (c + 2 < 16) {
            #pragma unroll 4
            for (int i = tid; i < 2048; i += 128) {
                int row = i >> 5, c16 = i & 31;
                const __nv_bfloat16* src = &g_cbh[(size_t)((c + 2) * 64 + row) * DIM + c16 * 8];
                CP_ASYNC16(Bbase + sw_off(row, c16), (const void*)src);
            }
            CP_COMMIT();
        }

        #pragma unroll
        for (int mt = 0; mt < 2; mt++) {
            #pragma unroll
            for (int nt = 0; nt < 4; nt++) {
                int col = c * 64 + wn * 32 + nt * 8 + ((lane & 3) << 1);
                float2 ne = nep[col >> 1];
                float dv[4];
                dv[0] = __fmaf_rn(-2.0f, C[mt][nt][0], ne.x);
                dv[1] = __fmaf_rn(-2.0f, C[mt][nt][1], ne.y);
                dv[2] = __fmaf_rn(-2.0f, C[mt][nt][2], ne.x);
                dv[3] = __fmaf_rn(-2.0f, C[mt][nt][3], ne.y);
                #pragma unroll
                for (int q = 0; q < 4; q++) {
                    const int s = mt * 2 + (q >> 1);
                    const int idx = col + (q & 1);
                    const float v = dv[q];
                    if (v < tv[s][2]) {
                        if (v < tv[s][1]) {
                            tv[s][2] = tv[s][1]; ts[s][2] = ts[s][1];
                            if (v < tv[s][0]) {
                                tv[s][1] = tv[s][0]; ts[s][1] = ts[s][0];
                                tv[s][0] = v;        ts[s][0] = idx;
                            } else { tv[s][1] = v; ts[s][1] = idx; }
                        } else { tv[s][2] = v; ts[s][2] = idx; }
                    }
                }
            }
        }
    }

    // ---- fused resolve + in-CTA exact rescore (B smem reused as scratch) ----
    float*  sV    = (float*)(smem + BS_OFF);               // 64*24 f32
    int*    sI    = (int*)  (smem + BS_OFF + 8192);
    float*  st1   = (float*)(smem + BS_OFF + 16384);       // 64 f32
    double* swl   = (double*)(smem + BS_OFF + 16896);      // 4 doubles
    int*    slist = (int*)  (smem + BS_OFF + 16960);       // ambiguous local rows
    int*    scnt  = (int*)  (smem + BS_OFF + 17224);

    if (tid == 0) *scnt = 0;
    if (tid < 64) st1[tid] = g_t1[m0 + tid];
    #pragma unroll
    for (int mt = 0; mt < 2; mt++) {
        #pragma unroll
        for (int h = 0; h < 2; h++) {
            int r    = wm * 32 + mt * 16 + h * 8 + (lane >> 2);
            int slot = wn * 4 + (lane & 3);
            int s = mt * 2 + h;
            #pragma unroll
            for (int j = 0; j < NSLOT; j++) {
                sV[r * 24 + slot * 3 + j] = tv[s][j];
                sI[r * 24 + slot * 3 + j] = ts[s][j];
            }
        }
    }
    __syncthreads();

    double lossAcc = 0.0;
    for (int rr = 0; rr < 16; rr++) {
        const int r = wid * 16 + rr;
        float v = (lane < NCROW) ? sV[r * 24 + lane] : 3.4e38f;
        int  ix = (lane < NCROW) ? sI[r * 24 + lane] : 0;
        float vmin = v;
        #pragma unroll
        for (int o = 16; o; o >>= 1) vmin = fminf(vmin, __shfl_xor_sync(0xffffffffu, vmin, o));
        unsigned m = __ballot_sync(0xffffffffu, v <= vmin + MARGIN);
        if (__popc(m) == 1) {
            int wl = __ffs(m) - 1;
            int bi   = __shfl_sync(0xffffffffu, ix, wl);
            float vw = __shfl_sync(0xffffffffu, v, wl);
            if (lane == 0) {
                g_idx[m0 + r] = bi;
                if (write_idx) out[IDX_OFF + m0 + r] = (float)bi;
                lossAcc += (double)(st1[r] + vw);      // approx dist; err ~3e-5 abs
            }
        } else {
            if (lane == 0) slist[atomicAdd(scnt, 1)] = r;
        }
    }
    __syncthreads();

    // in-CTA exact fp32 rescore of ambiguous rows.
    // z loaded from ORIGINAL [b,d,p] layout with the SAME d=lane*8..+7 per-lane
    // chain as the previously-passing rescore -> bit-identical dots.
    const int cnt = *scnt;
    for (int j = wid; j < cnt; j += 4) {
        const int r   = slist[j];
        const int row = m0 + r;
        float v = (lane < NCROW) ? sV[r * 24 + lane] : 3.4e38f;
        int  i1 = (lane < NCROW) ? sI[r * 24 + lane] : 0;
        float vmin = v;
        #pragma unroll
        for (int o = 16; o; o >>= 1) vmin = fminf(vmin, __shfl_xor_sync(0xffffffffu, vmin, o));
        unsigned m1 = __ballot_sync(0xffffffffu, v <= vmin + MARGIN);

        const int zb = row >> 10, zp = row & (HW - 1);
        const float* zbase = z + (size_t)zb * DIM * HW + zp;
        float z8[8];
        #pragma unroll
        for (int k = 0; k < 8; k++)
            z8[k] = zbase[(size_t)(lane * 8 + k) * HW];
        const float t1 = st1[r];
        float bestD = 3.4e38f;
        int bestI = 0x7fffffff;
        while (m1) {
            int l = __ffs(m1) - 1; m1 &= m1 - 1;
            int idx = __shfl_sync(0xffffffffu, i1, l);
            const float4* c4 = (const float4*)&cb[(size_t)idx * DIM + lane * 8];
            float4 ca = c4[0], cb4 = c4[1];
            float p = 0.0f;
            p = __fmaf_rn(z8[0], ca.x, p);  p = __fmaf_rn(z8[1], ca.y, p);
            p = __fmaf_rn(z8[2], ca.z, p);  p = __fmaf_rn(z8[3], ca.w, p);
            p = __fmaf_rn(z8[4], cb4.x, p); p = __fmaf_rn(z8[5], cb4.y, p);
            p = __fmaf_rn(z8[6], cb4.z, p); p = __fmaf_rn(z8[7], cb4.w, p);
            #pragma unroll
            for (int o = 16; o; o >>= 1) p += __shfl_xor_sync(0xffffffffu, p, o);
            float dd = __fsub_rn(__fadd_rn(t1, nef[idx]), __fmul_rn(2.0f, p));
            if (dd < bestD || (dd == bestD && idx < bestI)) { bestD = dd; bestI = idx; }
        }
        if (lane == 0) {
            g_idx[row] = bestI;
            if (write_idx) out[IDX_OFF + row] = (float)bestI;
            lossAcc += (double)bestD;                  // exact dist
        }
    }
    if (lane == 0) swl[wid] = lossAcc;
    __syncthreads();
    if (tid == 0) atomicAdd(&g_loss, swl[0] + swl[1] + swl[2] + swl[3]);
}

// ================= Kernel 3: gather z_q, d-split x8 blocks, float4 writes =======
__global__ __launch_bounds__(256) void gather_k(const float* __restrict__ z,
                                                const float* __restrict__ cb,
                                                float* __restrict__ out,
                                                int write_loss) {
    __shared__ float sq[64 * 33];      // [p][d_local], pad 33
    __shared__ int   sidx[64];
    const int n0 = blockIdx.x * 64;
    const int d0 = blockIdx.y * 32;
    const int b  = n0 >> 10, p0 = n0 & (HW - 1);
    const int tid = threadIdx.x;

    if (tid < 64) sidx[tid] = g_idx[n0 + tid];
    __syncthreads();
    #pragma unroll
    for (int i = tid; i < 512; i += 256) {
        int r = i >> 3, c4 = i & 7;
        float4 v = ((const float4*)cb)[(size_t)sidx[r] * 64 + (d0 >> 2) + c4];
        float* dst = &sq[r * 33 + c4 * 4];
        dst[0] = v.x; dst[1] = v.y; dst[2] = v.z; dst[3] = v.w;
    }
    __syncthreads();

    const int pq = tid & 15;
    const int dd = tid >> 4;
    const size_t base = (size_t)b * DIM * HW + p0 + pq * 4;
    #pragma unroll
    for (int ii = 0; ii < 2; ii++) {
        const int dl = ii * 16 + dd;
        const size_t off = base + (size_t)(d0 + dl) * HW;
        float4 zv = *(const float4*)&z[off];
        float q0 = sq[(pq * 4 + 0) * 33 + dl];
        float q1 = sq[(pq * 4 + 1) * 33 + dl];
        float q2 = sq[(pq * 4 + 2) * 33 + dl];
        float q3 = sq[(pq * 4 + 3) * 33 + dl];
        float4 o;
        float dx = __fsub_rn(q0, zv.x); o.x = __fadd_rn(zv.x, dx);
        float dy = __fsub_rn(q1, zv.y); o.y = __fadd_rn(zv.y, dy);
        float dz = __fsub_rn(q2, zv.z); o.z = __fadd_rn(zv.z, dz);
        float dw = __fsub_rn(q3, zv.w); o.w = __fadd_rn(zv.w, dw);
        *(float4*)&out[off] = o;                      // == reference STE per element
    }
    if (blockIdx.x == 0 && blockIdx.y == 0 && tid == 0 && write_loss)
        out[LOSS_OFF] = (float)(1.25 * g_loss / (double)ZQ_ELEMS);
}

extern "C" void kernel_launch(void* const* d_in, const int* in_sizes, int n_in,
                              void* d_out, int out_size) {
    const float* z  = (const float*)d_in[0];
    const float* cb = (const float*)d_in[1];
    float* out = (float*)d_out;

    cudaFuncSetAttribute(gemm_hmma_k, cudaFuncAttributeMaxDynamicSharedMemorySize, HM_SMEM);

    int write_idx  = (out_size >= IDX_OFF + NPTS);
    int write_loss = (out_size >= LOSS_OFF + 1);

    prep_k<<<1152, 256>>>(z, cb);
    gemm_hmma_k<<<NPTS / 64, 128, HM_SMEM>>>(z, cb, out, write_idx);
    gather_k<<<dim3(NPTS / 64, 8), 256>>>(z, cb, out, write_loss);
}

// round 17
// speedup vs baseline: 1.0179x; 1.0024x over previous
#include <cuda_runtime.h>
#include <cuda_bf16.h>
#include <cstdint>

// Problem constants
#define BATCH 32
#define DIM   256
#define HW    1024
#define NPTS  32768
#define KCODE 1024
#define ZQ_ELEMS 8388608
#define IDX_OFF  ZQ_ELEMS
#define LOSS_OFF (ZQ_ELEMS + NPTS)

#define NSLOT 3           // top-3 per (thread,row) slot
#define NCROW 24          // 8 slots * 3 candidates per row
#define MARGIN 7e-4f

// Scratch (device globals)
__device__ __nv_bfloat16  g_zth[NPTS * DIM];     // z^T bf16
__device__ __nv_bfloat16  g_cbh[KCODE * DIM];    // codebook bf16
__device__ int            g_idx[NPTS];
__device__ float          g_normE[KCODE];        // t2
__device__ float          g_t1[NPTS];            // t1 (sequential emulation)
__device__ double         g_loss;

// ================= generic PTX helpers =================
__device__ __forceinline__ uint32_t smem_u32(const void* p) {
    uint32_t a;
    asm("{ .reg .u64 t; cvta.to.shared.u64 t, %1; cvt.u32.u64 %0, t; }" : "=r"(a) : "l"(p));
    return a;
}
#define CP_ASYNC16(dst, src) \
    asm volatile("cp.async.cg.shared.global [%0], [%1], 16;" :: "r"(dst), "l"(src) : "memory")
#define CP_COMMIT() asm volatile("cp.async.commit_group;" ::: "memory")
#define CP_WAIT0()  asm volatile("cp.async.wait_group 0;" ::: "memory")
#define CP_WAIT1()  asm volatile("cp.async.wait_group 1;" ::: "memory")

#define LDSM4(r0, r1, r2, r3, addr) \
    asm volatile("ldmatrix.sync.aligned.m8n8.x4.shared.b16 {%0,%1,%2,%3}, [%4];" \
        : "=r"(r0), "=r"(r1), "=r"(r2), "=r"(r3) : "r"(addr))

#define MMA16816(C, A, b0, b1) \
    asm volatile("mma.sync.aligned.m16n8k16.row.col.f32.bf16.bf16.f32 " \
        "{%0,%1,%2,%3},{%4,%5,%6,%7},{%8,%9},{%0,%1,%2,%3};" \
        : "+f"((C)[0]), "+f"((C)[1]), "+f"((C)[2]), "+f"((C)[3]) \
        : "r"((A)[0]), "r"((A)[1]), "r"((A)[2]), "r"((A)[3]), "r"(b0), "r"(b1))

// swizzled smem offset for bf16 tile rows of 512B, 16B chunks
__device__ __forceinline__ uint32_t sw_off(int row, int c16) {
    return (uint32_t)(row * 512 + ((c16 ^ (row & 7)) << 4));
}

// ================= Kernel 1: FUSED prep (cvt+t1) + codebook norms ===============
// Vectorized: float4 z loads, 8B packed bf16 stores. Same values as before.
__global__ __launch_bounds__(256) void prep_k(const float* __restrict__ z,
                                              const float* __restrict__ cb) {
    const int bid = blockIdx.x;
    const int tid = threadIdx.x;
    if (bid < 1024) {
        __shared__ float sbuf[32][257];       // [p][d], 257: conflict-free phases
        const int b  = bid >> 5;
        const int p0 = (bid & 31) << 5;
        const float* src = z + (size_t)b * DIM * HW + p0;

        // load: thread = (p-quad pq, d-lane dly); 8 x LDG.128
        {
            const int pq  = tid & 7;          // positions pq*4 .. pq*4+3
            const int dly = tid >> 3;         // 0..31
            #pragma unroll
            for (int dp = 0; dp < 8; dp++) {
                const int d = dp * 32 + dly;
                float4 v = *(const float4*)&src[(size_t)d * HW + pq * 4];
                sbuf[pq * 4 + 0][d] = v.x;    // banks (4pq+k+dly)%32: permutation
                sbuf[pq * 4 + 1][d] = v.y;
                sbuf[pq * 4 + 2][d] = v.z;
                sbuf[pq * 4 + 3][d] = v.w;
            }
        }
        __syncthreads();

        const int n0 = (b << 10) + p0;
        // zth store: thread packs 4 consecutive d into one 8B store
        {
            const int dq = tid & 63;          // d = dq*4 .. dq*4+3
            const int pp = tid >> 6;          // 0..3
            #pragma unroll
            for (int it = 0; it < 8; it++) {
                const int p = it * 4 + pp;
                const float* row = &sbuf[p][dq * 4];
                __nv_bfloat162 h0 = __floats2bfloat162_rn(row[0], row[1]);
                __nv_bfloat162 h1 = __floats2bfloat162_rn(row[2], row[3]);
                uint2 u;
                u.x = *(uint32_t*)&h0; u.y = *(uint32_t*)&h1;
                *(uint2*)&g_zth[(size_t)(n0 + p) * DIM + dq * 4] = u;   // 256B/warp
            }
        }
        if (tid < 32) {
            const float* row = &sbuf[tid][0];
            float acc = 0.0f;
            #pragma unroll 8
            for (int d = 0; d < DIM; d++)
                acc = __fadd_rn(acc, __fmul_rn(row[d], row[d]));   // strict seq chain
            g_t1[n0 + tid] = acc;
        }
    } else {
        const int k    = ((bid - 1024) << 3) + (tid >> 5);
        const int lane = tid & 31;
        const float4* cp = (const float4*)&cb[(size_t)k * DIM + lane * 8];
        float4 a = cp[0], b4 = cp[1];
        __nv_bfloat162 h0 = __floats2bfloat162_rn(a.x, a.y);
        __nv_bfloat162 h1 = __floats2bfloat162_rn(a.z, a.w);
        __nv_bfloat162 h2 = __floats2bfloat162_rn(b4.x, b4.y);
        __nv_bfloat162 h3 = __floats2bfloat162_rn(b4.z, b4.w);
        uint4 u;
        u.x = *(uint32_t*)&h0; u.y = *(uint32_t*)&h1;
        u.z = *(uint32_t*)&h2; u.w = *(uint32_t*)&h3;
        ((uint4*)g_cbh)[(size_t)k * 32 + lane] = u;
        float s = 0.0f;
        s = __fmaf_rn(a.x, a.x, s);  s = __fmaf_rn(a.y, a.y, s);
        s = __fmaf_rn(a.z, a.z, s);  s = __fmaf_rn(a.w, a.w, s);
        s = __fmaf_rn(b4.x, b4.x, s); s = __fmaf_rn(b4.y, b4.y, s);
        s = __fmaf_rn(b4.z, b4.z, s); s = __fmaf_rn(b4.w, b4.w, s);
        #pragma unroll
        for (int o = 16; o; o >>= 1) s += __shfl_xor_sync(0xffffffffu, s, o);
        if (lane == 0) g_normE[k] = s;
        if (bid == 1024 && tid == 0) g_loss = 0.0;
    }
}

// ================= Kernel 2: HMMA bf16 GEMM + full in-CTA resolve & rescore =====
// smem: A 32KB | B0 32KB | B1 32KB | NE 4KB = 100KB -> 2 CTAs/SM
#define AS_OFF 0
#define BS_OFF 32768
#define NE_OFF 98304
#define HM_SMEM 102400

__global__ __launch_bounds__(128, 2) void gemm_hmma_k(const float* __restrict__ z,
                                                      const float* __restrict__ cb,
                                                      float* __restrict__ out, int write_idx) {
    extern __shared__ char smem[];
    const uint32_t sb = smem_u32(smem);
    const int tid  = threadIdx.x;
    const int lane = tid & 31;
    const int wid  = tid >> 5;
    const int wm   = wid & 1;
    const int wn   = wid >> 1;
    const int m0   = blockIdx.x * 64;

    #pragma unroll 4
    for (int i = tid; i < 2048; i += 128) {
        int row = i >> 5, c16 = i & 31;
        const __nv_bfloat16* src = &g_zth[(size_t)(m0 + row) * DIM + c16 * 8];
        CP_ASYNC16(sb + AS_OFF + sw_off(row, c16), (const void*)src);
    }
    #pragma unroll 4
    for (int i = tid; i < 2048; i += 128) {
        int row = i >> 5, c16 = i & 31;
        const __nv_bfloat16* src = &g_cbh[(size_t)row * DIM + c16 * 8];
        CP_ASYNC16(sb + BS_OFF + sw_off(row, c16), (const void*)src);
    }
    #pragma unroll
    for (int i = tid; i < 256; i += 128)
        CP_ASYNC16(sb + NE_OFF + i * 16, (const void*)&g_normE[i * 4]);
    CP_COMMIT();
    #pragma unroll 4
    for (int i = tid; i < 2048; i += 128) {
        int row = i >> 5, c16 = i & 31;
        const __nv_bfloat16* src = &g_cbh[(size_t)(64 + row) * DIM + c16 * 8];
        CP_ASYNC16(sb + BS_OFF + 32768 + sw_off(row, c16), (const void*)src);
    }
    CP_COMMIT();

    float tv[4][NSLOT];
    int   ts[4][NSLOT];
    #pragma unroll
    for (int s = 0; s < 4; s++)
        #pragma unroll
        for (int j = 0; j < NSLOT; j++) { tv[s][j] = 3.4e38f; ts[s][j] = 0; }

    const float2* nep = (const float2*)(smem + NE_OFF);
    const float*  nef = (const float*)(smem + NE_OFF);

    const int arow = wm * 32 + (lane & 15);
    const int acol_sel = (lane >> 4);
    const int brow0 = wn * 32 + ((lane >> 4) & 1) * 8 + (lane & 7);
    const int bcol_sel = ((lane >> 3) & 1);

    for (int c = 0; c < 16; ++c) {
        if (c < 15) CP_WAIT1(); else CP_WAIT0();
        __syncthreads();

        const uint32_t Bbase = sb + BS_OFF + ((c & 1) << 15);
        float C[2][4][4];
        #pragma unroll
        for (int mt = 0; mt < 2; mt++)
            #pragma unroll
            for (int nt = 0; nt < 4; nt++)
                #pragma unroll
                for (int q = 0; q < 4; q++) C[mt][nt][q] = 0.0f;

        uint32_t a[2][2][4], b[2][2][4];
        {
            int c16 = acol_sel;
            LDSM4(a[0][0][0], a[0][0][1], a[0][0][2], a[0][0][3], sb + AS_OFF + sw_off(arow,      c16));
            LDSM4(a[0][1][0], a[0][1][1], a[0][1][2], a[0][1][3], sb + AS_OFF + sw_off(arow + 16, c16));
            int bc = bcol_sel;
            LDSM4(b[0][0][0], b[0][0][1], b[0][0][2], b[0][0][3], Bbase + sw_off(brow0,      bc));
            LDSM4(b[0][1][0], b[0][1][1], b[0][1][2], b[0][1][3], Bbase + sw_off(brow0 + 16, bc));
        }

        #pragma unroll
        for (int st = 0; st < 16; ++st) {
            const int cur = st & 1, nxt = cur ^ 1;
            if (st < 15) {
                int c16 = (st + 1) * 2 + acol_sel;
                LDSM4(a[nxt][0][0], a[nxt][0][1], a[nxt][0][2], a[nxt][0][3], sb + AS_OFF + sw_off(arow,      c16));
                LDSM4(a[nxt][1][0], a[nxt][1][1], a[nxt][1][2], a[nxt][1][3], sb + AS_OFF + sw_off(arow + 16, c16));
                int bc = (st + 1) * 2 + bcol_sel;
                LDSM4(b[nxt][0][0], b[nxt][0][1], b[nxt][0][2], b[nxt][0][3], Bbase + sw_off(brow0,      bc));
                LDSM4(b[nxt][1][0], b[nxt][1][1], b[nxt][1][2], b[nxt][1][3], Bbase + sw_off(brow0 + 16, bc));
            }
            #pragma unroll
            for (int mt = 0; mt < 2; mt++)
                #pragma unroll
                for (int nt = 0; nt < 4; nt++)
                    MMA16816(C[mt][nt], a[cur][mt], b[cur][nt >> 1][(nt & 1) * 2], b[cur][nt >> 1][(nt & 1) * 2 + 1]);
        }
        __syncthreads();

        if (c + 2 < 16) {
            #pragma unroll 4
            for (int i = tid; i < 2048; i += 128) {
                int row = i >> 5, c16 = i & 31;
                const __nv_bfloat16* src = &g_cbh[(size_t)((c + 2) * 64 + row) * DIM + c16 * 8];
                CP_ASYNC16(Bbase + sw_off(row, c16), (const void*)src);
            }
            CP_COMMIT();
        }

        #pragma unroll
        for (int mt = 0; mt < 2; mt++) {
            #pragma unroll
            for (int nt = 0; nt < 4; nt++) {
                int col = c * 64 + wn * 32 + nt * 8 + ((lane & 3) << 1);
                float2 ne = nep[col >> 1];
                float dv[4];
                dv[0] = __fmaf_rn(-2.0f, C[mt][nt][0], ne.x);
                dv[1] = __fmaf_rn(-2.0f, C[mt][nt][1], ne.y);
                dv[2] = __fmaf_rn(-2.0f, C[mt][nt][2], ne.x);
                dv[3] = __fmaf_rn(-2.0f, C[mt][nt][3], ne.y);
                #pragma unroll
                for (int q = 0; q < 4; q++) {
                    const int s = mt * 2 + (q >> 1);
                    const int idx = col + (q & 1);
                    const float v = dv[q];
                    if (v < tv[s][2]) {
                        if (v < tv[s][1]) {
                            tv[s][2] = tv[s][1]; ts[s][2] = ts[s][1];
                            if (v < tv[s][0]) {
                                tv[s][1] = tv[s][0]; ts[s][1] = ts[s][0];
                                tv[s][0] = v;        ts[s][0] = idx;
                            } else { tv[s][1] = v; ts[s][1] = idx; }
                        } else { tv[s][2] = v; ts[s][2] = idx; }
                    }
                }
            }
        }
    }

    // ---- fused resolve + in-CTA exact rescore (B smem reused as scratch) ----
    float*  sV    = (float*)(smem + BS_OFF);               // 64*24 f32
    int*    sI    = (int*)  (smem + BS_OFF + 8192);
    float*  st1   = (float*)(smem + BS_OFF + 16384);       // 64 f32
    double* swl   = (double*)(smem + BS_OFF + 16896);      // 4 doubles
    int*    slist = (int*)  (smem + BS_OFF + 16960);       // ambiguous local rows
    int*    scnt  = (int*)  (smem + BS_OFF + 17224);

    if (tid == 0) *scnt = 0;
    if (tid < 64) st1[tid] = g_t1[m0 + tid];
    #pragma unroll
    for (int mt = 0; mt < 2; mt++) {
        #pragma unroll
        for (int h = 0; h < 2; h++) {
            int r    = wm * 32 + mt * 16 + h * 8 + (lane >> 2);
            int slot = wn * 4 + (lane & 3);
            int s = mt * 2 + h;
            #pragma unroll
            for (int j = 0; j < NSLOT; j++) {
                sV[r * 24 + slot * 3 + j] = tv[s][j];
                sI[r * 24 + slot * 3 + j] = ts[s][j];
            }
        }
    }
    __syncthreads();

    double lossAcc = 0.0;
    for (int rr = 0; rr < 16; rr++) {
        const int r = wid * 16 + rr;
        float v = (lane < NCROW) ? sV[r * 24 + lane] : 3.4e38f;
        int  ix = (lane < NCROW) ? sI[r * 24 + lane] : 0;
        float vmin = v;
        #pragma unroll
        for (int o = 16; o; o >>= 1) vmin = fminf(vmin, __shfl_xor_sync(0xffffffffu, vmin, o));
        unsigned m = __ballot_sync(0xffffffffu, v <= vmin + MARGIN);
        if (__popc(m) == 1) {
            int wl = __ffs(m) - 1;
            int bi   = __shfl_sync(0xffffffffu, ix, wl);
            float vw = __shfl_sync(0xffffffffu, v, wl);
            if (lane == 0) {
                g_idx[m0 + r] = bi;
                if (write_idx) out[IDX_OFF + m0 + r] = (float)bi;
                lossAcc += (double)(st1[r] + vw);      // approx dist; err ~3e-5 abs
            }
        } else {
            if (lane == 0) slist[atomicAdd(scnt, 1)] = r;
        }
    }
    __syncthreads();

    // in-CTA exact fp32 rescore of ambiguous rows (z read from original layout).
    const int cnt = *scnt;
    for (int j = wid; j < cnt; j += 4) {
        const int r   = slist[j];
        const int row = m0 + r;
        float v = (lane < NCROW) ? sV[r * 24 + lane] : 3.4e38f;
        int  i1 = (lane < NCROW) ? sI[r * 24 + lane] : 0;
        float vmin = v;
        #pragma unroll
        for (int o = 16; o; o >>= 1) vmin = fminf(vmin, __shfl_xor_sync(0xffffffffu, vmin, o));
        unsigned m1 = __ballot_sync(0xffffffffu, v <= vmin + MARGIN);

        const int zb = row >> 10, zp = row & (HW - 1);
        const float* zbase = z + (size_t)zb * DIM * HW + zp;
        float z8[8];
        #pragma unroll
        for (int k = 0; k < 8; k++)
            z8[k] = zbase[(size_t)(lane * 8 + k) * HW];
        const float t1 = st1[r];
        float bestD = 3.4e38f;
        int bestI = 0x7fffffff;
        while (m1) {
            int l = __ffs(m1) - 1; m1 &= m1 - 1;
            int idx = __shfl_sync(0xffffffffu, i1, l);
            const float4* c4 = (const float4*)&cb[(size_t)idx * DIM + lane * 8];
            float4 ca = c4[0], cb4 = c4[1];
            float p = 0.0f;
            p = __fmaf_rn(z8[0], ca.x, p);  p = __fmaf_rn(z8[1], ca.y, p);
            p = __fmaf_rn(z8[2], ca.z, p);  p = __fmaf_rn(z8[3], ca.w, p);
            p = __fmaf_rn(z8[4], cb4.x, p); p = __fmaf_rn(z8[5], cb4.y, p);
            p = __fmaf_rn(z8[6], cb4.z, p); p = __fmaf_rn(z8[7], cb4.w, p);
            #pragma unroll
            for (int o = 16; o; o >>= 1) p += __shfl_xor_sync(0xffffffffu, p, o);
            float dd = __fsub_rn(__fadd_rn(t1, nef[idx]), __fmul_rn(2.0f, p));
            if (dd < bestD || (dd == bestD && idx < bestI)) { bestD = dd; bestI = idx; }
        }
        if (lane == 0) {
            g_idx[row] = bestI;
            if (write_idx) out[IDX_OFF + row] = (float)bestI;
            lossAcc += (double)bestD;                  // exact dist
        }
    }
    if (lane == 0) swl[wid] = lossAcc;
    __syncthreads();
    if (tid == 0) atomicAdd(&g_loss, swl[0] + swl[1] + swl[2] + swl[3]);
}

// ================= Kernel 3: gather z_q, d-split x8 blocks, float4 writes =======
__global__ __launch_bounds__(256) void gather_k(const float* __restrict__ z,
                                                const float* __restrict__ cb,
                                                float* __restrict__ out,
                                                int write_loss) {
    __shared__ float sq[64 * 33];      // [p][d_local], pad 33
    __shared__ int   sidx[64];
    const int n0 = blockIdx.x * 64;
    const int d0 = blockIdx.y * 32;
    const int b  = n0 >> 10, p0 = n0 & (HW - 1);
    const int tid = threadIdx.x;

    if (tid < 64) sidx[tid] = g_idx[n0 + tid];
    __syncthreads();
    #pragma unroll
    for (int i = tid; i < 512; i += 256) {
        int r = i >> 3, c4 = i & 7;
        float4 v = ((const float4*)cb)[(size_t)sidx[r] * 64 + (d0 >> 2) + c4];
        float* dst = &sq[r * 33 + c4 * 4];
        dst[0] = v.x; dst[1] = v.y; dst[2] = v.z; dst[3] = v.w;
    }
    __syncthreads();

    const int pq = tid & 15;
    const int dd = tid >> 4;
    const size_t base = (size_t)b * DIM * HW + p0 + pq * 4;
    #pragma unroll
    for (int ii = 0; ii < 2; ii++) {
        const int dl = ii * 16 + dd;
        const size_t off = base + (size_t)(d0 + dl) * HW;
        float4 zv = *(const float4*)&z[off];
        float q0 = sq[(pq * 4 + 0) * 33 + dl];
        float q1 = sq[(pq * 4 + 1) * 33 + dl];
        float q2 = sq[(pq * 4 + 2) * 33 + dl];
        float q3 = sq[(pq * 4 + 3) * 33 + dl];
        float4 o;
        float dx = __fsub_rn(q0, zv.x); o.x = __fadd_rn(zv.x, dx);
        float dy = __fsub_rn(q1, zv.y); o.y = __fadd_rn(zv.y, dy);
        float dz = __fsub_rn(q2, zv.z); o.z = __fadd_rn(zv.z, dz);
        float dw = __fsub_rn(q3, zv.w); o.w = __fadd_rn(zv.w, dw);
        *(float4*)&out[off] = o;                      // == reference STE per element
    }
    if (blockIdx.x == 0 && blockIdx.y == 0 && tid == 0 && write_loss)
        out[LOSS_OFF] = (float)(1.25 * g_loss / (double)ZQ_ELEMS);
}

extern "C" void kernel_launch(void* const* d_in, const int* in_sizes, int n_in,
                              void* d_out, int out_size) {
    const float* z  = (const float*)d_in[0];
    const float* cb = (const float*)d_in[1];
    float* out = (float*)d_out;

    cudaFuncSetAttribute(gemm_hmma_k, cudaFuncAttributeMaxDynamicSharedMemorySize, HM_SMEM);

    int write_idx  = (out_size >= IDX_OFF + NPTS);
    int write_loss = (out_size >= LOSS_OFF + 1);

    prep_k<<<1152, 256>>>(z, cb);
    gemm_hmma_k<<<NPTS / 64, 128, HM_SMEM>>>(z, cb, out, write_idx);
    gather_k<<<dim3(NPTS / 64, 8), 256>>>(z, cb, out, write_loss);
}